// round 1
// baseline (speedup 1.0000x reference)
#include <cuda_runtime.h>
#include <math.h>

// ---------------- problem constants ----------------
constexpr int NH = 16, DH = 64, DM = 1024;
constexpr int QL = 1024, ML = 1024, KL = 2048, BS = 4;

// ---------------- scratch (device globals; no allocation) ----------------
__device__ float g_Qw[(size_t)BS*NH*QL*DH];   // (q + r_w_bias) * 0.125, [b][n][i][d]
__device__ float g_K [(size_t)BS*NH*KL*DH];   // [b][n][j][d]
__device__ float g_V [(size_t)BS*NH*KL*DH];   // [b][n][j][d]
__device__ float g_R [(size_t)NH*KL*DH];      // [n][j][d]
__device__ float g_av[(size_t)QL*BS*DM];      // attn_vec rows m = i*4+b
__device__ float g_tmp[(size_t)QL*BS*DM];     // w + attn_out (pre-LN)

// ---------------- generic tile params ----------------
constexpr int BM = 128, BN = 64, BK = 16;

// ============ Kernel A: QKV projection (cat @ qkv_w^T) with scatter ============
__global__ void __launch_bounds__(256) qkv_kernel(const float* __restrict__ mems,
                                                  const float* __restrict__ w,
                                                  const float* __restrict__ qkv_w,
                                                  const float* __restrict__ rw_b) {
    __shared__ __align__(16) float As[BK][BM + 4];
    __shared__ __align__(16) float Bs[BK][BN + 4];
    const int bm = blockIdx.y * BM;       // over M = 8192 (m = k2*4 + b)
    const int bn = blockIdx.x * BN;       // over N = 3072
    const int t = threadIdx.x;
    const int tx = t & 15, ty = t >> 4;

    float acc[8][4];
#pragma unroll
    for (int i = 0; i < 8; i++)
#pragma unroll
        for (int j = 0; j < 4; j++) acc[i][j] = 0.f;

    for (int k0 = 0; k0 < DM; k0 += BK) {
#pragma unroll
        for (int u = 0; u < 2; u++) {
            int g = t + u * 256;                   // 0..511
            int row = g >> 2, c4 = g & 3;
            int m = bm + row;
            const float* Arow = (m < 4096) ? (mems + (size_t)m * DM)
                                           : (w + (size_t)(m - 4096) * DM);
            float4 v = *(const float4*)(Arow + k0 + c4 * 4);
            As[c4 * 4 + 0][row] = v.x; As[c4 * 4 + 1][row] = v.y;
            As[c4 * 4 + 2][row] = v.z; As[c4 * 4 + 3][row] = v.w;
        }
        {
            int row = t >> 2, c4 = t & 3;
            float4 v = *(const float4*)(qkv_w + (size_t)(bn + row) * DM + k0 + c4 * 4);
            Bs[c4 * 4 + 0][row] = v.x; Bs[c4 * 4 + 1][row] = v.y;
            Bs[c4 * 4 + 2][row] = v.z; Bs[c4 * 4 + 3][row] = v.w;
        }
        __syncthreads();
#pragma unroll
        for (int k = 0; k < BK; k++) {
            float a[8], b4[4];
            *(float4*)&a[0] = *(const float4*)&As[k][ty * 8];
            *(float4*)&a[4] = *(const float4*)&As[k][ty * 8 + 4];
            *(float4*)&b4[0] = *(const float4*)&Bs[k][tx * 4];
#pragma unroll
            for (int ii = 0; ii < 8; ii++)
#pragma unroll
                for (int jj = 0; jj < 4; jj++) acc[ii][jj] = fmaf(a[ii], b4[jj], acc[ii][jj]);
        }
        __syncthreads();
    }
    // scatter epilogue
#pragma unroll
    for (int ii = 0; ii < 8; ii++) {
        int m = bm + ty * 8 + ii;
        int k2 = m >> 2, b = m & 3;
#pragma unroll
        for (int jj = 0; jj < 4; jj++) {
            int oc = bn + tx * 4 + jj;
            float v = acc[ii][jj];
            int region = oc >> 10;
            int oo = oc & 1023;
            int n = oo >> 6, d = oo & 63;
            if (region == 0) {
                if (k2 >= ML) {
                    int i = k2 - ML;
                    g_Qw[((size_t)(b * NH + n) * QL + i) * DH + d] = (v + rw_b[oo]) * 0.125f;
                }
            } else if (region == 1) {
                g_K[((size_t)(b * NH + n) * KL + k2) * DH + d] = v;
            } else {
                g_V[((size_t)(b * NH + n) * KL + k2) * DH + d] = v;
            }
        }
    }
}

// ============ Kernel B: R projection (r @ r_net_w^T) with scatter ============
__global__ void __launch_bounds__(256) r_kernel(const float* __restrict__ r,
                                                const float* __restrict__ r_net_w) {
    __shared__ __align__(16) float As[BK][BM + 4];
    __shared__ __align__(16) float Bs[BK][BN + 4];
    const int bm = blockIdx.y * BM;       // over 2048
    const int bn = blockIdx.x * BN;       // over 1024
    const int t = threadIdx.x;
    const int tx = t & 15, ty = t >> 4;

    float acc[8][4];
#pragma unroll
    for (int i = 0; i < 8; i++)
#pragma unroll
        for (int j = 0; j < 4; j++) acc[i][j] = 0.f;

    for (int k0 = 0; k0 < DM; k0 += BK) {
#pragma unroll
        for (int u = 0; u < 2; u++) {
            int g = t + u * 256;
            int row = g >> 2, c4 = g & 3;
            float4 v = *(const float4*)(r + (size_t)(bm + row) * DM + k0 + c4 * 4);
            As[c4 * 4 + 0][row] = v.x; As[c4 * 4 + 1][row] = v.y;
            As[c4 * 4 + 2][row] = v.z; As[c4 * 4 + 3][row] = v.w;
        }
        {
            int row = t >> 2, c4 = t & 3;
            float4 v = *(const float4*)(r_net_w + (size_t)(bn + row) * DM + k0 + c4 * 4);
            Bs[c4 * 4 + 0][row] = v.x; Bs[c4 * 4 + 1][row] = v.y;
            Bs[c4 * 4 + 2][row] = v.z; Bs[c4 * 4 + 3][row] = v.w;
        }
        __syncthreads();
#pragma unroll
        for (int k = 0; k < BK; k++) {
            float a[8], b4[4];
            *(float4*)&a[0] = *(const float4*)&As[k][ty * 8];
            *(float4*)&a[4] = *(const float4*)&As[k][ty * 8 + 4];
            *(float4*)&b4[0] = *(const float4*)&Bs[k][tx * 4];
#pragma unroll
            for (int ii = 0; ii < 8; ii++)
#pragma unroll
                for (int jj = 0; jj < 4; jj++) acc[ii][jj] = fmaf(a[ii], b4[jj], acc[ii][jj]);
        }
        __syncthreads();
    }
#pragma unroll
    for (int ii = 0; ii < 8; ii++) {
        int j = bm + ty * 8 + ii;
#pragma unroll
        for (int jj = 0; jj < 4; jj++) {
            int oc = bn + tx * 4 + jj;
            int n = oc >> 6, d = oc & 63;
            g_R[((size_t)n * KL + j) * DH + d] = acc[ii][jj];
        }
    }
}

// ============ Kernel C: fused rel-attention (flash-style) ============
constexpr int TI = 128, TJ = 16, RB = 144, RST = 68;

__global__ void __launch_bounds__(128) attn_kernel(const float* __restrict__ rr_bias,
                                                   const float* __restrict__ rw_bias) {
    __shared__ __align__(16) float Ks[TJ * RST];
    __shared__ __align__(16) float Vs[TJ * RST];
    __shared__ __align__(16) float Rs[RB * RST];
    __shared__ float brr[RB];
    __shared__ float dbs[DH];

    const int i0 = blockIdx.x * TI;
    const int b = blockIdx.y, n = blockIdx.z;
    const int t = threadIdx.x;

    if (t < DH) dbs[t] = (rr_bias[n * DH + t] - rw_bias[n * DH + t]) * 0.125f;

    const float* Qp = g_Qw + ((size_t)(b * NH + n) * QL + i0 + t) * DH;
    float4 q[16];
#pragma unroll
    for (int c = 0; c < 16; c++) q[c] = ((const float4*)Qp)[c];

    float4 o[16];
#pragma unroll
    for (int c = 0; c < 16; c++) o[c] = make_float4(0.f, 0.f, 0.f, 0.f);
    float mrun = -1e30f, lrun = 0.f;

    const float* Kp = g_K + (size_t)(b * NH + n) * KL * DH;
    const float* Vp = g_V + (size_t)(b * NH + n) * KL * DH;
    const float* Rp = g_R + (size_t)n * KL * DH;

    const int i = i0 + t;
    const int jlim = i + ML;                              // inclusive
    const int jmax = min(KL, i0 + TI - 1 + ML + 1);       // exclusive (mult of 16)

    for (int j0 = 0; j0 < jmax; j0 += TJ) {
        __syncthreads();
#pragma unroll
        for (int u = 0; u < 2; u++) {
            int g = t + u * 128;
            int row = g >> 4, c4 = g & 15;
            ((float4*)Ks)[row * 17 + c4] = ((const float4*)(Kp + (size_t)(j0 + row) * DH))[c4];
            ((float4*)Vs)[row * 17 + c4] = ((const float4*)(Vp + (size_t)(j0 + row) * DH))[c4];
        }
        const int rel_base = j0 - i0 + 896;
#pragma unroll
        for (int u = 0; u < 18; u++) {
            int g = t + u * 128;
            int row = g >> 4, c4 = g & 15;
            int rel = rel_base + row;
            rel = (rel > KL - 1) ? (KL - 1) : rel;
            ((float4*)Rs)[row * 17 + c4] = ((const float4*)(Rp + (size_t)rel * DH))[c4];
        }
        __syncthreads();
        for (int row = t; row < RB; row += 128) {
            float a = 0.f;
            const float* rr = Rs + row * RST;
#pragma unroll
            for (int c = 0; c < DH; c++) a = fmaf(dbs[c], rr[c], a);
            brr[row] = a;
        }
        __syncthreads();

        float s[TJ];
#pragma unroll
        for (int rj = 0; rj < TJ; rj++) {
            const float4* kr = (const float4*)Ks + rj * 17;
            const int row = rj + (TI - 1) - t;            // 0..142
            const float4* rr = (const float4*)Rs + row * 17;
            float4 acc = make_float4(0.f, 0.f, 0.f, 0.f);
#pragma unroll
            for (int c = 0; c < 16; c++) {
                float4 k4 = kr[c], r4 = rr[c], q4 = q[c];
                acc.x = fmaf(q4.x, k4.x, acc.x); acc.x = fmaf(q4.x, r4.x, acc.x);
                acc.y = fmaf(q4.y, k4.y, acc.y); acc.y = fmaf(q4.y, r4.y, acc.y);
                acc.z = fmaf(q4.z, k4.z, acc.z); acc.z = fmaf(q4.z, r4.z, acc.z);
                acc.w = fmaf(q4.w, k4.w, acc.w); acc.w = fmaf(q4.w, r4.w, acc.w);
            }
            float sv = (acc.x + acc.y) + (acc.z + acc.w) + brr[row];
            s[rj] = (j0 + rj > jlim) ? -1e30f : sv;
        }
        float tmax = s[0];
#pragma unroll
        for (int rj = 1; rj < TJ; rj++) tmax = fmaxf(tmax, s[rj]);
        float mnew = fmaxf(mrun, tmax);
        float corr = __expf(mrun - mnew);
        lrun *= corr;
#pragma unroll
        for (int c = 0; c < 16; c++) {
            o[c].x *= corr; o[c].y *= corr; o[c].z *= corr; o[c].w *= corr;
        }
#pragma unroll
        for (int rj = 0; rj < TJ; rj++) {
            float p = __expf(s[rj] - mnew);
            lrun += p;
            const float4* vr = (const float4*)Vs + rj * 17;
#pragma unroll
            for (int c = 0; c < 16; c++) {
                float4 v4 = vr[c];
                o[c].x = fmaf(p, v4.x, o[c].x);
                o[c].y = fmaf(p, v4.y, o[c].y);
                o[c].z = fmaf(p, v4.z, o[c].z);
                o[c].w = fmaf(p, v4.w, o[c].w);
            }
        }
        mrun = mnew;
    }

    const float inv = 1.f / lrun;
    float4* op = (float4*)(g_av + (size_t)((i0 + t) * BS + b) * DM + n * DH);
#pragma unroll
    for (int c = 0; c < 16; c++) {
        float4 v = o[c];
        op[c] = make_float4(v.x * inv, v.y * inv, v.z * inv, v.w * inv);
    }
}

// ============ Kernel D: output projection + residual ============
__global__ void __launch_bounds__(256) o_kernel(const float* __restrict__ o_w,
                                                const float* __restrict__ w) {
    __shared__ __align__(16) float As[BK][BM + 4];
    __shared__ __align__(16) float Bs[BK][BN + 4];
    const int bm = blockIdx.y * BM;       // over 4096
    const int bn = blockIdx.x * BN;       // over 1024
    const int t = threadIdx.x;
    const int tx = t & 15, ty = t >> 4;

    float acc[8][4];
#pragma unroll
    for (int i = 0; i < 8; i++)
#pragma unroll
        for (int j = 0; j < 4; j++) acc[i][j] = 0.f;

    for (int k0 = 0; k0 < DM; k0 += BK) {
#pragma unroll
        for (int u = 0; u < 2; u++) {
            int g = t + u * 256;
            int row = g >> 2, c4 = g & 3;
            float4 v = *(const float4*)(g_av + (size_t)(bm + row) * DM + k0 + c4 * 4);
            As[c4 * 4 + 0][row] = v.x; As[c4 * 4 + 1][row] = v.y;
            As[c4 * 4 + 2][row] = v.z; As[c4 * 4 + 3][row] = v.w;
        }
        {
            int row = t >> 2, c4 = t & 3;
            float4 v = *(const float4*)(o_w + (size_t)(bn + row) * DM + k0 + c4 * 4);
            Bs[c4 * 4 + 0][row] = v.x; Bs[c4 * 4 + 1][row] = v.y;
            Bs[c4 * 4 + 2][row] = v.z; Bs[c4 * 4 + 3][row] = v.w;
        }
        __syncthreads();
#pragma unroll
        for (int k = 0; k < BK; k++) {
            float a[8], b4[4];
            *(float4*)&a[0] = *(const float4*)&As[k][ty * 8];
            *(float4*)&a[4] = *(const float4*)&As[k][ty * 8 + 4];
            *(float4*)&b4[0] = *(const float4*)&Bs[k][tx * 4];
#pragma unroll
            for (int ii = 0; ii < 8; ii++)
#pragma unroll
                for (int jj = 0; jj < 4; jj++) acc[ii][jj] = fmaf(a[ii], b4[jj], acc[ii][jj]);
        }
        __syncthreads();
    }
#pragma unroll
    for (int ii = 0; ii < 8; ii++) {
        int m = bm + ty * 8 + ii;
#pragma unroll
        for (int jj = 0; jj < 4; jj++) {
            int oc = bn + tx * 4 + jj;
            g_tmp[(size_t)m * DM + oc] = acc[ii][jj] + w[(size_t)m * DM + oc];
        }
    }
}

// ============ Kernel E: LayerNorm ============
__global__ void __launch_bounds__(256) ln_kernel(const float* __restrict__ gamma,
                                                 const float* __restrict__ beta,
                                                 float* __restrict__ out) {
    const int row = blockIdx.x;
    const float* x = g_tmp + (size_t)row * DM;
    float s = 0.f, ss = 0.f;
#pragma unroll
    for (int u = 0; u < 4; u++) {
        float v = x[threadIdx.x + u * 256];
        s += v; ss += v * v;
    }
#pragma unroll
    for (int off = 16; off; off >>= 1) {
        s += __shfl_xor_sync(0xffffffffu, s, off);
        ss += __shfl_xor_sync(0xffffffffu, ss, off);
    }
    __shared__ float sm_s[8], sm_ss[8];
    int wid = threadIdx.x >> 5, lid = threadIdx.x & 31;
    if (lid == 0) { sm_s[wid] = s; sm_ss[wid] = ss; }
    __syncthreads();
    if (threadIdx.x == 0) {
        float a = 0.f, b2 = 0.f;
#pragma unroll
        for (int i2 = 0; i2 < 8; i2++) { a += sm_s[i2]; b2 += sm_ss[i2]; }
        sm_s[0] = a; sm_ss[0] = b2;
    }
    __syncthreads();
    const float mu = sm_s[0] * (1.f / DM);
    const float var = sm_ss[0] * (1.f / DM) - mu * mu;
    const float inv = rsqrtf(var + 1e-5f);
#pragma unroll
    for (int u = 0; u < 4; u++) {
        int c = threadIdx.x + u * 256;
        out[(size_t)row * DM + c] = (x[c] - mu) * inv * gamma[c] + beta[c];
    }
}

// ============ launch ============
extern "C" void kernel_launch(void* const* d_in, const int* in_sizes, int n_in,
                              void* d_out, int out_size) {
    const float* w       = (const float*)d_in[0];   // [1024,4,1024]
    const float* r       = (const float*)d_in[1];   // [2048,1024]
    const float* mems    = (const float*)d_in[2];   // [1024,4,1024]
    // d_in[3] = attn_mask  (unused; mask computed analytically: j > i + MLEN)
    const float* qkv_w   = (const float*)d_in[4];   // [3072,1024]
    const float* r_net_w = (const float*)d_in[5];   // [1024,1024]
    const float* o_w     = (const float*)d_in[6];   // [1024,1024]
    const float* rr_bias = (const float*)d_in[7];   // [16,64]
    const float* rw_bias = (const float*)d_in[8];   // [16,64]
    const float* ln_g    = (const float*)d_in[9];   // [1024]
    const float* ln_b    = (const float*)d_in[10];  // [1024]
    float* out = (float*)d_out;

    qkv_kernel<<<dim3(48, 64), 256>>>(mems, w, qkv_w, rw_bias);
    r_kernel<<<dim3(16, 16), 256>>>(r, r_net_w);
    attn_kernel<<<dim3(8, 4, 16), 128>>>(rr_bias, rw_bias);
    o_kernel<<<dim3(16, 32), 256>>>(o_w, w);
    ln_kernel<<<4096, 256>>>(ln_g, ln_b, out);
}